// round 10
// baseline (speedup 1.0000x reference)
#include <cuda_runtime.h>

// Problem constants
#define NVAR 14
#define CCAT 2
#define EDIM 32
#define VNUM 3
#define DDIM 16
#define KSZ  3
#define KSTATES 16384      // 2^14
#define BBATCH 32

#define H1CH 32            // conv1 out channels (2*D)
#define H1SP 9             // 3x3
#define H1N  (H1CH*H1SP)   // 288
#define H2CH 16            // conv2 out channels (D)
#define H2SP 25            // 5x5
#define H2N  (H2CH*H2SP)   // 400
#define W2N  (H2CH*KSZ*KSZ) // 144 entries per input channel
#define MN   49            // 7x7
#define XPAD 52            // padded x row (16B-aligned float4 rows)

#define WARPS 8
#define BLOCKS_PER_V 148
#define TOTAL_WARPS_PER_V (BLOCKS_PER_V*WARPS)        // 1184
#define QSTATES (KSTATES / TOTAL_WARPS_PER_V)         // 13
#define RSTATES (KSTATES - QSTATES*TOTAL_WARPS_PER_V) // 992

// Precomputed scratch (no allocations allowed)
__device__ float g_B1[VNUM*NVAR*CCAT*H1N];
__device__ float g_C1[VNUM*H1N];
__device__ float g_D1[VNUM*NVAR*H1N];   // delta per bit position b (0..13)
__device__ float g_E1[VNUM*H1N];        // base = C1 + sum_j B1[j,0]

// ---------------------------------------------------------------------------
// Precompute B1[v,j,c,:] = (latent[j,c] @ lin_w[v, j*ED:(j+1)*ED, :]) @ W1[v]
// ---------------------------------------------------------------------------
__global__ void precompute_B1_kernel(const float* __restrict__ lat,
                                     const float* __restrict__ lin_w,
                                     const float* __restrict__ w1) {
    int b = blockIdx.x;            // v*NVAR*CCAT + j*CCAT + c
    int v = b / (NVAR*CCAT);
    int jc = b % (NVAR*CCAT);
    int j = jc / CCAT, c = jc % CCAT;
    __shared__ float A[4*DDIM];    // 64
    int t = threadIdx.x;
    if (t < 4*DDIM) {
        float a = 0.f;
        const float* L = lat + (j*CCAT + c)*EDIM;
        const float* W = lin_w + (size_t)v*(NVAR*EDIM*4*DDIM) + (size_t)(j*EDIM)*(4*DDIM) + t;
        #pragma unroll
        for (int e = 0; e < EDIM; e++) a += L[e] * W[e*(4*DDIM)];
        A[t] = a;
    }
    __syncthreads();
    if (t < H1N) {
        float s = 0.f;
        const float* W1 = w1 + (size_t)v*(4*DDIM*H1N) + t;
        #pragma unroll 8
        for (int i = 0; i < 4*DDIM; i++) s += A[i] * W1[i*H1N];
        g_B1[(size_t)b*H1N + t] = s;
    }
}

__global__ void precompute_C1_kernel(const float* __restrict__ lin_b,
                                     const float* __restrict__ w1,
                                     const float* __restrict__ b1) {
    int v = blockIdx.x;
    int t = threadIdx.x;           // 0..287
    float s = b1[v*H1CH + t/H1SP];
    const float* W1 = w1 + (size_t)v*(4*DDIM*H1N) + t;
    const float* lb = lin_b + v*(4*DDIM);
    #pragma unroll 8
    for (int i = 0; i < 4*DDIM; i++) s += lb[i] * W1[i*H1N];
    g_C1[v*H1N + t] = s;
}

// D1[v, b, :] = B1[v, j=13-b, 1, :] - B1[v, j=13-b, 0, :]
// E1[v, :]    = C1[v, :] + sum_j B1[v, j, 0, :]
__global__ void precompute_D1E1_kernel() {
    int v = blockIdx.x;
    int t = threadIdx.x;  // 0..287
    float e = g_C1[v*H1N + t];
    #pragma unroll
    for (int j = 0; j < NVAR; j++) {
        float b0 = g_B1[(size_t)((v*NVAR + j)*CCAT + 0)*H1N + t];
        float b1v = g_B1[(size_t)((v*NVAR + j)*CCAT + 1)*H1N + t];
        e += b0;
        int b = NVAR - 1 - j;    // bit position for variable j
        g_D1[(size_t)(v*NVAR + b)*H1N + t] = b1v - b0;
    }
    g_E1[v*H1N + t] = e;
}

// ---------------------------------------------------------------------------
// Main kernel: one warp per contiguous state range; per-v constants in shared.
// ---------------------------------------------------------------------------

// shared layout in floats (all vector-accessed region starts are 16B aligned)
#define S_D1  0
#define S_E1  (S_D1 + NVAR*H1N)           // +4032  -> 4032
#define S_W2T (S_E1 + H1N)                // +288   -> 4320 (transposed w2)
#define S_W3  (S_W2T + H1CH*W2N)          // +4608  -> 8928
#define S_B2  (S_W3 + H2CH*12)            // +192   -> 9120
#define S_X   (S_B2 + 16)                 // +16    -> 9136
#define S_H1S (S_X + BBATCH*XPAD)         // +1664  -> 10800
#define S_H2  (S_H1S + WARPS*H1CH*12)     // +3072  -> 13872
#define S_M   (S_H2 + WARPS*H2N)          // +3200  -> 17072
#define S_BUF (S_M + WARPS*XPAD)          // +416   -> 17488
#define SMEM_FLOATS (S_BUF + WARPS*160)   // +1280  -> 18768 floats = 75072 B

__device__ __forceinline__ float elu_f(float x) {
    return x > 0.f ? x : (__expf(x) - 1.f);
}

__global__ void __launch_bounds__(WARPS*32, 3)
emission_main_kernel(const float* __restrict__ x,
                     const float* __restrict__ w2,
                     const float* __restrict__ b2,
                     const float* __restrict__ w3,
                     const float* __restrict__ b3,
                     float* __restrict__ out) {
    extern __shared__ float smem[];
    const int tid  = threadIdx.x;
    const int lane = tid & 31;
    const int warp = tid >> 5;
    const int v    = blockIdx.x / BLOCKS_PER_V;
    const int blk  = blockIdx.x % BLOCKS_PER_V;

    // ---- stage in per-v constants ----
    for (int i = tid; i < NVAR*H1N; i += blockDim.x)
        smem[S_D1 + i] = g_D1[(size_t)v*(NVAR*H1N) + i];
    for (int i = tid; i < H1N; i += blockDim.x)
        smem[S_E1 + i] = g_E1[v*H1N + i];
    // w2 transposed per channel: dst i*144 + lane*4 + k  holds  w2[i][k*32+lane]
    // (k<4); tail entries 128..143 stored straight.
    for (int j = tid; j < H1CH*W2N; j += blockDim.x) {
        int i = j / W2N, e = j % W2N;
        int dst = (e < 128) ? (i*W2N + (e & 31)*4 + (e >> 5)) : (i*W2N + e);
        smem[S_W2T + dst] = w2[(size_t)v*(H1CH*W2N) + j];
    }
    // w3 padded: 9 taps per channel stored in 12-float rows (rows 16B aligned)
    if (tid < H2CH*KSZ*KSZ) {
        int i = tid / 9, t = tid % 9;
        smem[S_W3 + i*12 + t] = w3[(size_t)v*(H2CH*KSZ*KSZ) + tid];
    }
    if (tid < H2CH) smem[S_B2 + tid] = b2[v*H2CH + tid];
    for (int i = tid; i < BBATCH*MN; i += blockDim.x) {
        int bb = i / MN, p = i % MN;
        smem[S_X + bb*XPAD + p] = x[(size_t)bb*(VNUM*MN) + v*MN + p];
    }
    __syncthreads();

    float* __restrict__ sD1 = smem + S_D1;
    float* __restrict__ sE1 = smem + S_E1;
    float* __restrict__ sW2 = smem + S_W2T;
    float* __restrict__ sW3 = smem + S_W3;
    float* __restrict__ sB2 = smem + S_B2;
    float* __restrict__ sX  = smem + S_X;
    float* __restrict__ h1w = smem + S_H1S + warp*(H1CH*12);
    float* __restrict__ h2w = smem + S_H2 + warp*H2N;
    float* __restrict__ mw  = smem + S_M  + warp*XPAD;
    float* __restrict__ buf = smem + S_BUF + warp*160;
    const float bias3 = b3[v];

    // contiguous state range for this warp
    const int wid    = blk*WARPS + warp;
    const int nst    = QSTATES + (wid < RSTATES ? 1 : 0);
    const int start  = wid*QSTATES + (wid < RSTATES ? wid : RSTATES);

    // ---- build initial pre-ELU h1 in registers ----
    float h1pre[9];
    {
        const float* ep = sE1 + lane*H1SP;
        #pragma unroll
        for (int q = 0; q < 9; q++) h1pre[q] = ep[q];
        #pragma unroll
        for (int b = 0; b < NVAR; b++) {
            if ((start >> b) & 1) {
                const float* dp = sD1 + b*H1N + lane*H1SP;
                #pragma unroll
                for (int q = 0; q < 9; q++) h1pre[q] += dp[q];
            }
        }
    }

    for (int g0 = 0; g0 < nst; g0 += 4) {
        const int gs = (nst - g0 < 4) ? (nst - g0) : 4;
        const int s0 = start + g0;

        for (int si = 0; si < gs; si++) {
            const int s = s0 + si;

            // ---- incremental update: flip the bits that changed ----
            if (g0 + si) {
                unsigned diff = (unsigned)(s ^ (s - 1));
                do {
                    int b = __ffs(diff) - 1;
                    diff &= diff - 1;
                    float sg = ((s >> b) & 1) ? 1.f : -1.f;
                    const float* dp = sD1 + b*H1N + lane*H1SP;
                    #pragma unroll
                    for (int q = 0; q < 9; q++) h1pre[q] = fmaf(sg, dp[q], h1pre[q]);
                } while (diff);
            }

            // ---- ELU + publish h1 (lane = channel) to padded smem row ----
            {
                float4 p0, p1;
                p0.x = elu_f(h1pre[0]); p0.y = elu_f(h1pre[1]);
                p0.z = elu_f(h1pre[2]); p0.w = elu_f(h1pre[3]);
                p1.x = elu_f(h1pre[4]); p1.y = elu_f(h1pre[5]);
                p1.z = elu_f(h1pre[6]); p1.w = elu_f(h1pre[7]);
                float p8 = elu_f(h1pre[8]);
                float* row = h1w + lane*12;
                *(float4*)(row)     = p0;
                *(float4*)(row + 4) = p1;
                row[8] = p8;
            }

            // ---- zero h2 accumulator (vectorized) ----
            {
                float4 z4 = make_float4(0.f, 0.f, 0.f, 0.f);
                for (int idx = lane; idx < H2N/4; idx += 32)
                    *(float4*)(h2w + idx*4) = z4;
            }
            __syncwarp();

            // ---- conv2 as 9 K=32 -> N=144 products in registers ----
            float acc[5][9];
            #pragma unroll
            for (int k = 0; k < 5; k++)
                #pragma unroll
                for (int q = 0; q < 9; q++) acc[k][q] = 0.f;

            #pragma unroll 4
            for (int i = 0; i < H1CH; i++) {
                const float* hrow = h1w + i*12;
                float4 ha = *(const float4*)(hrow);
                float4 hb = *(const float4*)(hrow + 4);
                float  hc = hrow[8];
                const float* wrow = sW2 + i*W2N;
                float4 wv = *(const float4*)(wrow + lane*4);
                float wr4 = (lane < 16) ? wrow[128 + lane] : 0.f;
                #pragma unroll
                for (int k = 0; k < 5; k++) {
                    float w = (k==0)?wv.x:(k==1)?wv.y:(k==2)?wv.z:(k==3)?wv.w:wr4;
                    acc[k][0] += w * ha.x;
                    acc[k][1] += w * ha.y;
                    acc[k][2] += w * ha.z;
                    acc[k][3] += w * ha.w;
                    acc[k][4] += w * hb.x;
                    acc[k][5] += w * hb.y;
                    acc[k][6] += w * hb.z;
                    acc[k][7] += w * hb.w;
                    acc[k][8] += w * hc;
                }
            }

            // ---- scatter into h2 (all 144 targets distinct within each q) ----
            #pragma unroll
            for (int q = 0; q < 9; q++) {
                const int u = q / 3, vx = q % 3;
                #pragma unroll
                for (int k = 0; k < 5; k++) {
                    const int e = lane + 32*k;
                    if (e < W2N) {
                        const int o = e / 9, t = e % 9;
                        const int ky = t / 3, kx = t % 3;
                        h2w[o*H2SP + (u+ky)*5 + (vx+kx)] += acc[k][q];
                    }
                }
                __syncwarp();
            }

            // ---- init m with bias3 ----
            for (int idx = lane; idx < MN; idx += 32)
                mw[idx] = bias3;
            __syncwarp();

            // ---- conv3: lane = input position; bias+ELU fused ----
            if (lane < H2SP) {
                const int u  = lane / 5, vv = lane % 5;
                float4 b2a = *(const float4*)(sB2);
                float4 b2b = *(const float4*)(sB2 + 4);
                float4 b2c = *(const float4*)(sB2 + 8);
                float4 b2d = *(const float4*)(sB2 + 12);
                float b2r[16] = {b2a.x,b2a.y,b2a.z,b2a.w, b2b.x,b2b.y,b2b.z,b2b.w,
                                 b2c.x,b2c.y,b2c.z,b2c.w, b2d.x,b2d.y,b2d.z,b2d.w};
                float val[9];
                #pragma unroll
                for (int t = 0; t < 9; t++) val[t] = 0.f;
                #pragma unroll
                for (int i = 0; i < H2CH; i++) {
                    float h = elu_f(h2w[i*H2SP + lane] + b2r[i]);
                    const float* wrow = sW3 + i*12;
                    float4 wA = *(const float4*)(wrow);
                    float4 wB = *(const float4*)(wrow + 4);
                    float  w8 = wrow[8];
                    val[0] += h * wA.x;
                    val[1] += h * wA.y;
                    val[2] += h * wA.z;
                    val[3] += h * wA.w;
                    val[4] += h * wB.x;
                    val[5] += h * wB.y;
                    val[6] += h * wB.z;
                    val[7] += h * wB.w;
                    val[8] += h * w8;
                }
                #pragma unroll
                for (int t = 0; t < 9; t++) {
                    const int ky = t / 3, kx = t % 3;
                    mw[(u+ky)*7 + (vv+kx)] += val[t];   // distinct addrs per round
                    __syncwarp(0x01ffffffu);
                }
            }
            __syncwarp();

            // ---- loss vs all 32 images: lane = batch index ----
            {
                float accb = 0.f;
                const float* xp = sX + lane*XPAD;
                #pragma unroll
                for (int j = 0; j < 12; j++) {
                    float4 mv = *(const float4*)(mw + 4*j);
                    float4 xv = *(const float4*)(xp + 4*j);
                    float d0 = mv.x - xv.x;
                    float d1 = mv.y - xv.y;
                    float d2 = mv.z - xv.z;
                    float d3 = mv.w - xv.w;
                    accb += d0*d0 + d1*d1 + d2*d2 + d3*d3;
                }
                float d48 = mw[48] - xp[48];
                accb += d48*d48;
                buf[si*40 + lane] = -0.5f * accb;   // lane = batch
            }
            __syncwarp();
        }

        // ---- coalesced flush of the group: (b, si) -> out[b, s0+si, v] ----
        if (gs == 4) {
            #pragma unroll
            for (int r = 0; r < 4; r++) {
                int idx = r*32 + lane;
                int b  = idx >> 2;
                int si = idx & 3;
                out[(size_t)b*(KSTATES*VNUM) + (size_t)(s0+si)*VNUM + v] =
                    buf[si*40 + b];
            }
        } else {
            for (int idx = lane; idx < gs*32; idx += 32) {
                int b  = idx / gs;
                int si = idx % gs;
                out[(size_t)b*(KSTATES*VNUM) + (size_t)(s0+si)*VNUM + v] =
                    buf[si*40 + b];
            }
        }
        __syncwarp();
    }
}

// ---------------------------------------------------------------------------
extern "C" void kernel_launch(void* const* d_in, const int* in_sizes, int n_in,
                              void* d_out, int out_size) {
    const float* x     = (const float*)d_in[0];
    const float* lat   = (const float*)d_in[1];
    const float* lin_w = (const float*)d_in[2];
    const float* lin_b = (const float*)d_in[3];
    const float* w1    = (const float*)d_in[4];
    const float* b1    = (const float*)d_in[5];
    const float* w2    = (const float*)d_in[6];
    const float* b2    = (const float*)d_in[7];
    const float* w3    = (const float*)d_in[8];
    const float* b3    = (const float*)d_in[9];
    float* out = (float*)d_out;

    (void)in_sizes; (void)n_in; (void)out_size;

    precompute_B1_kernel<<<VNUM*NVAR*CCAT, H1N>>>(lat, lin_w, w1);
    precompute_C1_kernel<<<VNUM, H1N>>>(lin_b, w1, b1);
    precompute_D1E1_kernel<<<VNUM, H1N>>>();

    cudaFuncSetAttribute(emission_main_kernel,
                         cudaFuncAttributeMaxDynamicSharedMemorySize,
                         SMEM_FLOATS * (int)sizeof(float));

    emission_main_kernel<<<VNUM*BLOCKS_PER_V, WARPS*32, SMEM_FLOATS*sizeof(float)>>>(
        x, w2, b2, w3, b3, out);
}

// round 11
// speedup vs baseline: 1.0436x; 1.0436x over previous
#include <cuda_runtime.h>

// Problem constants
#define NVAR 14
#define CCAT 2
#define EDIM 32
#define VNUM 3
#define DDIM 16
#define KSZ  3
#define KSTATES 16384      // 2^14
#define BBATCH 32

#define H1CH 32            // conv1 out channels (2*D)
#define H1SP 9             // 3x3
#define H1N  (H1CH*H1SP)   // 288
#define H2CH 16            // conv2 out channels (D)
#define H2SP 25            // 5x5
#define H2N  (H2CH*H2SP)   // 400
#define W2N  (H2CH*KSZ*KSZ) // 144 entries per input channel
#define MN   49            // 7x7
#define MROW 52            // padded m row (16B-aligned float4 rows)
#define GRP  4             // states per loss group

#define WARPS 8
#define BLOCKS_PER_V 148
#define TOTAL_WARPS_PER_V (BLOCKS_PER_V*WARPS)        // 1184
#define QSTATES (KSTATES / TOTAL_WARPS_PER_V)         // 13
#define RSTATES (KSTATES - QSTATES*TOTAL_WARPS_PER_V) // 992

// Precomputed scratch (no allocations allowed)
__device__ float g_B1[VNUM*NVAR*CCAT*H1N];
__device__ float g_C1[VNUM*H1N];
__device__ float g_D1[VNUM*NVAR*H1N];   // delta per bit position b (0..13)
__device__ float g_E1[VNUM*H1N];        // base = C1 + sum_j B1[j,0]

// ---------------------------------------------------------------------------
// Precompute B1[v,j,c,:] = (latent[j,c] @ lin_w[v, j*ED:(j+1)*ED, :]) @ W1[v]
// ---------------------------------------------------------------------------
__global__ void precompute_B1_kernel(const float* __restrict__ lat,
                                     const float* __restrict__ lin_w,
                                     const float* __restrict__ w1) {
    int b = blockIdx.x;            // v*NVAR*CCAT + j*CCAT + c
    int v = b / (NVAR*CCAT);
    int jc = b % (NVAR*CCAT);
    int j = jc / CCAT, c = jc % CCAT;
    __shared__ float A[4*DDIM];    // 64
    int t = threadIdx.x;
    if (t < 4*DDIM) {
        float a = 0.f;
        const float* L = lat + (j*CCAT + c)*EDIM;
        const float* W = lin_w + (size_t)v*(NVAR*EDIM*4*DDIM) + (size_t)(j*EDIM)*(4*DDIM) + t;
        #pragma unroll
        for (int e = 0; e < EDIM; e++) a += L[e] * W[e*(4*DDIM)];
        A[t] = a;
    }
    __syncthreads();
    if (t < H1N) {
        float s = 0.f;
        const float* W1 = w1 + (size_t)v*(4*DDIM*H1N) + t;
        #pragma unroll 8
        for (int i = 0; i < 4*DDIM; i++) s += A[i] * W1[i*H1N];
        g_B1[(size_t)b*H1N + t] = s;
    }
}

__global__ void precompute_C1_kernel(const float* __restrict__ lin_b,
                                     const float* __restrict__ w1,
                                     const float* __restrict__ b1) {
    int v = blockIdx.x;
    int t = threadIdx.x;           // 0..287
    float s = b1[v*H1CH + t/H1SP];
    const float* W1 = w1 + (size_t)v*(4*DDIM*H1N) + t;
    const float* lb = lin_b + v*(4*DDIM);
    #pragma unroll 8
    for (int i = 0; i < 4*DDIM; i++) s += lb[i] * W1[i*H1N];
    g_C1[v*H1N + t] = s;
}

// D1[v, b, :] = B1[v, j=13-b, 1, :] - B1[v, j=13-b, 0, :]
// E1[v, :]    = C1[v, :] + sum_j B1[v, j, 0, :]
__global__ void precompute_D1E1_kernel() {
    int v = blockIdx.x;
    int t = threadIdx.x;  // 0..287
    float e = g_C1[v*H1N + t];
    #pragma unroll
    for (int j = 0; j < NVAR; j++) {
        float b0 = g_B1[(size_t)((v*NVAR + j)*CCAT + 0)*H1N + t];
        float b1v = g_B1[(size_t)((v*NVAR + j)*CCAT + 1)*H1N + t];
        e += b0;
        int b = NVAR - 1 - j;    // bit position for variable j
        g_D1[(size_t)(v*NVAR + b)*H1N + t] = b1v - b0;
    }
    g_E1[v*H1N + t] = e;
}

// ---------------------------------------------------------------------------
// Main kernel: one warp per contiguous state range; per-v constants in shared.
// ---------------------------------------------------------------------------

// shared layout in floats (all vector-accessed region starts are 16B aligned)
#define S_D1  0
#define S_E1  (S_D1 + NVAR*H1N)           // +4032  -> 4032
#define S_W2  (S_E1 + H1N)                // +288   -> 4320
#define S_W3  (S_W2 + H1CH*W2N)           // +4608  -> 8928
#define S_B2  (S_W3 + H2CH*12)            // +192   -> 9120
#define S_X   (S_B2 + 16)                 // +16    -> 9136
#define S_H1S (S_X + BBATCH*MN)           // +1568  -> 10704 (16-float aligned)
#define S_H2  (S_H1S + WARPS*H1CH*12)     // +3072  -> 13776
#define S_M   (S_H2 + WARPS*H2N)          // +3200  -> 16976
#define SMEM_FLOATS (S_M + WARPS*GRP*MROW) // +1664 -> 18640 floats = 74560 B

__device__ __forceinline__ float elu_f(float x) {
    return x > 0.f ? x : (__expf(x) - 1.f);
}

__global__ void __launch_bounds__(WARPS*32, 3)
emission_main_kernel(const float* __restrict__ x,
                     const float* __restrict__ w2,
                     const float* __restrict__ b2,
                     const float* __restrict__ w3,
                     const float* __restrict__ b3,
                     float* __restrict__ out) {
    extern __shared__ float smem[];
    const int tid  = threadIdx.x;
    const int lane = tid & 31;
    const int warp = tid >> 5;
    const int v    = blockIdx.x / BLOCKS_PER_V;
    const int blk  = blockIdx.x % BLOCKS_PER_V;

    // ---- stage in per-v constants ----
    for (int i = tid; i < NVAR*H1N; i += blockDim.x)
        smem[S_D1 + i] = g_D1[(size_t)v*(NVAR*H1N) + i];
    for (int i = tid; i < H1N; i += blockDim.x)
        smem[S_E1 + i] = g_E1[v*H1N + i];
    for (int i = tid; i < H1CH*W2N; i += blockDim.x)
        smem[S_W2 + i] = w2[(size_t)v*(H1CH*W2N) + i];
    // w3 padded: 9 taps per channel stored in 12-float rows (rows 16B aligned)
    if (tid < H2CH*KSZ*KSZ) {
        int i = tid / 9, t = tid % 9;
        smem[S_W3 + i*12 + t] = w3[(size_t)v*(H2CH*KSZ*KSZ) + tid];
    }
    if (tid < H2CH) smem[S_B2 + tid] = b2[v*H2CH + tid];
    for (int i = tid; i < BBATCH*MN; i += blockDim.x) {
        int bb = i / MN, p = i % MN;
        smem[S_X + i] = x[(size_t)bb*(VNUM*MN) + v*MN + p];
    }
    __syncthreads();

    float* __restrict__ sD1 = smem + S_D1;
    float* __restrict__ sE1 = smem + S_E1;
    float* __restrict__ sW2 = smem + S_W2;
    float* __restrict__ sW3 = smem + S_W3;
    float* __restrict__ sB2 = smem + S_B2;
    float* __restrict__ sX  = smem + S_X;
    float* __restrict__ h1w = smem + S_H1S + warp*(H1CH*12);
    float* __restrict__ h2w = smem + S_H2 + warp*H2N;
    float* __restrict__ mg  = smem + S_M  + warp*(GRP*MROW);
    const float bias3 = b3[v];

    // hoisted loop-invariant b2 registers (conv3 uses lanes < 25 only)
    float b2r[16];
    {
        float4 b2a = *(const float4*)(sB2);
        float4 b2b = *(const float4*)(sB2 + 4);
        float4 b2c = *(const float4*)(sB2 + 8);
        float4 b2d = *(const float4*)(sB2 + 12);
        b2r[0]=b2a.x;  b2r[1]=b2a.y;  b2r[2]=b2a.z;  b2r[3]=b2a.w;
        b2r[4]=b2b.x;  b2r[5]=b2b.y;  b2r[6]=b2b.z;  b2r[7]=b2b.w;
        b2r[8]=b2c.x;  b2r[9]=b2c.y;  b2r[10]=b2c.z; b2r[11]=b2c.w;
        b2r[12]=b2d.x; b2r[13]=b2d.y; b2r[14]=b2d.z; b2r[15]=b2d.w;
    }

    // contiguous state range for this warp
    const int wid    = blk*WARPS + warp;
    const int nst    = QSTATES + (wid < RSTATES ? 1 : 0);
    const int start  = wid*QSTATES + (wid < RSTATES ? wid : RSTATES);

    // ---- build initial pre-ELU h1 in registers ----
    float h1pre[9];
    {
        const float* ep = sE1 + lane*H1SP;
        #pragma unroll
        for (int q = 0; q < 9; q++) h1pre[q] = ep[q];
        #pragma unroll
        for (int b = 0; b < NVAR; b++) {
            if ((start >> b) & 1) {
                const float* dp = sD1 + b*H1N + lane*H1SP;
                #pragma unroll
                for (int q = 0; q < 9; q++) h1pre[q] += dp[q];
            }
        }
    }

    for (int g0 = 0; g0 < nst; g0 += GRP) {
        const int gs = (nst - g0 < GRP) ? (nst - g0) : GRP;
        const int s0 = start + g0;

        for (int si = 0; si < gs; si++) {
            const int s = s0 + si;
            float* __restrict__ mw = mg + si*MROW;

            // ---- incremental update: flip the bits that changed (avg ~2) ----
            if (g0 + si) {
                unsigned diff = (unsigned)(s ^ (s - 1));
                do {
                    int b = __ffs(diff) - 1;
                    diff &= diff - 1;
                    float sg = ((s >> b) & 1) ? 1.f : -1.f;
                    const float* dp = sD1 + b*H1N + lane*H1SP;
                    #pragma unroll
                    for (int q = 0; q < 9; q++) h1pre[q] = fmaf(sg, dp[q], h1pre[q]);
                } while (diff);
            }

            // ---- ELU + publish h1 (lane = channel) to padded smem row ----
            {
                float4 p0, p1;
                p0.x = elu_f(h1pre[0]); p0.y = elu_f(h1pre[1]);
                p0.z = elu_f(h1pre[2]); p0.w = elu_f(h1pre[3]);
                p1.x = elu_f(h1pre[4]); p1.y = elu_f(h1pre[5]);
                p1.z = elu_f(h1pre[6]); p1.w = elu_f(h1pre[7]);
                float p8 = elu_f(h1pre[8]);
                float* row = h1w + lane*12;
                *(float4*)(row)     = p0;
                *(float4*)(row + 4) = p1;
                row[8] = p8;
            }

            // ---- zero h2 accumulator (bias folded into conv3's ELU load) ----
            for (int idx = lane; idx < H2N; idx += 32)
                h2w[idx] = 0.f;
            __syncwarp();

            // ---- conv2 as 9 K=32 -> N=144 products, accumulated in regs;
            //      h1 row broadcast via float4 loads (no shfl) ----
            float acc[5][9];
            #pragma unroll
            for (int k = 0; k < 5; k++)
                #pragma unroll
                for (int q = 0; q < 9; q++) acc[k][q] = 0.f;

            #pragma unroll 4
            for (int i = 0; i < H1CH; i++) {
                const float* hrow = h1w + i*12;
                float4 ha = *(const float4*)(hrow);
                float4 hb = *(const float4*)(hrow + 4);
                float  hc = hrow[8];
                const float* wrow = sW2 + i*W2N;
                float wr0 = wrow[lane];
                float wr1 = wrow[lane + 32];
                float wr2 = wrow[lane + 64];
                float wr3 = wrow[lane + 96];
                float wr4 = (lane < 16) ? wrow[lane + 128] : 0.f;
                #pragma unroll
                for (int k = 0; k < 5; k++) {
                    float w = (k==0)?wr0:(k==1)?wr1:(k==2)?wr2:(k==3)?wr3:wr4;
                    acc[k][0] += w * ha.x;
                    acc[k][1] += w * ha.y;
                    acc[k][2] += w * ha.z;
                    acc[k][3] += w * ha.w;
                    acc[k][4] += w * hb.x;
                    acc[k][5] += w * hb.y;
                    acc[k][6] += w * hb.z;
                    acc[k][7] += w * hb.w;
                    acc[k][8] += w * hc;
                }
            }

            // ---- scatter into h2 (all 144 targets distinct within each q) ----
            #pragma unroll
            for (int q = 0; q < 9; q++) {
                const int u = q / 3, vx = q % 3;
                #pragma unroll
                for (int k = 0; k < 5; k++) {
                    const int e = lane + 32*k;
                    if (e < W2N) {
                        const int o = e / 9, t = e % 9;
                        const int ky = t / 3, kx = t % 3;
                        h2w[o*H2SP + (u+ky)*5 + (vx+kx)] += acc[k][q];
                    }
                }
                __syncwarp();
            }

            // ---- init m with bias3 ----
            for (int idx = lane; idx < MN; idx += 32)
                mw[idx] = bias3;
            __syncwarp();

            // ---- conv3: lane = input position; bias+ELU fused; broadcast
            //      float4 weight loads; 9 conflict-free RMW scatter rounds ----
            if (lane < H2SP) {
                const int u  = lane / 5, vv = lane % 5;
                float val[9];
                #pragma unroll
                for (int t = 0; t < 9; t++) val[t] = 0.f;
                #pragma unroll
                for (int i = 0; i < H2CH; i++) {
                    float h = elu_f(h2w[i*H2SP + lane] + b2r[i]);
                    const float* wrow = sW3 + i*12;
                    float4 wA = *(const float4*)(wrow);
                    float4 wB = *(const float4*)(wrow + 4);
                    float  w8 = wrow[8];
                    val[0] += h * wA.x;
                    val[1] += h * wA.y;
                    val[2] += h * wA.z;
                    val[3] += h * wA.w;
                    val[4] += h * wB.x;
                    val[5] += h * wB.y;
                    val[6] += h * wB.z;
                    val[7] += h * wB.w;
                    val[8] += h * w8;
                }
                #pragma unroll
                for (int t = 0; t < 9; t++) {
                    const int ky = t / 3, kx = t % 3;
                    mw[(u+ky)*7 + (vv+kx)] += val[t];   // distinct addrs per round
                    __syncwarp(0x01ffffffu);
                }
            }
            __syncwarp();
        }

        // ---- group loss vs all 32 images: lane = batch; x read ONCE per
        //      group, m rows via broadcast float4 loads ----
        {
            float accb[GRP];
            #pragma unroll
            for (int si = 0; si < GRP; si++) accb[si] = 0.f;
            const float* xp = sX + lane*MN;

            if (gs == GRP) {
                #pragma unroll
                for (int j = 0; j < 12; j++) {
                    float x0 = xp[4*j + 0];
                    float x1 = xp[4*j + 1];
                    float x2 = xp[4*j + 2];
                    float x3 = xp[4*j + 3];
                    #pragma unroll
                    for (int si = 0; si < GRP; si++) {
                        float4 mv = *(const float4*)(mg + si*MROW + 4*j);
                        float d0 = mv.x - x0;
                        float d1 = mv.y - x1;
                        float d2 = mv.z - x2;
                        float d3 = mv.w - x3;
                        accb[si] += d0*d0 + d1*d1 + d2*d2 + d3*d3;
                    }
                }
                float x48 = xp[48];
                #pragma unroll
                for (int si = 0; si < GRP; si++) {
                    float d = mg[si*MROW + 48] - x48;
                    accb[si] += d*d;
                    out[(size_t)lane*(KSTATES*VNUM) + (size_t)(s0+si)*VNUM + v] =
                        -0.5f * (accb[si]);
                }
            } else {
                for (int si = 0; si < gs; si++) {
                    float a = 0.f;
                    const float* mp = mg + si*MROW;
                    #pragma unroll 7
                    for (int p = 0; p < MN; p++) {
                        float d = mp[p] - xp[p];
                        a += d*d;
                    }
                    out[(size_t)lane*(KSTATES*VNUM) + (size_t)(s0+si)*VNUM + v] =
                        -0.5f * a;
                }
            }
        }
        __syncwarp();
    }
}

// ---------------------------------------------------------------------------
extern "C" void kernel_launch(void* const* d_in, const int* in_sizes, int n_in,
                              void* d_out, int out_size) {
    const float* x     = (const float*)d_in[0];
    const float* lat   = (const float*)d_in[1];
    const float* lin_w = (const float*)d_in[2];
    const float* lin_b = (const float*)d_in[3];
    const float* w1    = (const float*)d_in[4];
    const float* b1    = (const float*)d_in[5];
    const float* w2    = (const float*)d_in[6];
    const float* b2    = (const float*)d_in[7];
    const float* w3    = (const float*)d_in[8];
    const float* b3    = (const float*)d_in[9];
    float* out = (float*)d_out;

    (void)in_sizes; (void)n_in; (void)out_size;

    precompute_B1_kernel<<<VNUM*NVAR*CCAT, H1N>>>(lat, lin_w, w1);
    precompute_C1_kernel<<<VNUM, H1N>>>(lin_b, w1, b1);
    precompute_D1E1_kernel<<<VNUM, H1N>>>();

    cudaFuncSetAttribute(emission_main_kernel,
                         cudaFuncAttributeMaxDynamicSharedMemorySize,
                         SMEM_FLOATS * (int)sizeof(float));

    emission_main_kernel<<<VNUM*BLOCKS_PER_V, WARPS*32, SMEM_FLOATS*sizeof(float)>>>(
        x, w2, b2, w3, b3, out);
}

// round 14
// speedup vs baseline: 1.0792x; 1.0341x over previous
#include <cuda_runtime.h>

// Problem constants
#define NVAR 14
#define CCAT 2
#define EDIM 32
#define VNUM 3
#define DDIM 16
#define KSZ  3
#define KSTATES 16384      // 2^14
#define BBATCH 32

#define H1CH 32            // conv1 out channels (2*D)
#define H1SP 9             // 3x3
#define H1N  (H1CH*H1SP)   // 288
#define H2CH 16            // conv2 out channels (D)
#define H2SP 25            // 5x5
#define H2N  (H2CH*H2SP)   // 400
#define W2N  (H2CH*KSZ*KSZ) // 144 entries per input channel
#define MN   49            // 7x7
#define MROW 52            // padded m row (16B-aligned float4 rows)
#define GRP  4             // states per loss group

#define WARPS 8
#define BLOCKS_PER_V 148
#define TOTAL_WARPS_PER_V (BLOCKS_PER_V*WARPS)        // 1184
#define QSTATES (KSTATES / TOTAL_WARPS_PER_V)         // 13
#define RSTATES (KSTATES - QSTATES*TOTAL_WARPS_PER_V) // 992

// Packed f32x2 helpers (Blackwell): 2 fp32 MACs per fma-pipe issue slot.
#define FMA2(d, a, b, c) \
    asm("fma.rn.f32x2 %0, %1, %2, %3;" : "=l"(d) : "l"(a), "l"(b), "l"(c))
#define PACK2(out, f) \
    asm("mov.b64 %0, {%1, %1};" : "=l"(out) : "f"(f))
#define UNPK2(lo, hi, in) \
    asm("mov.b64 {%0, %1}, %2;" : "=f"(lo), "=f"(hi) : "l"(in))

// Precomputed scratch (no allocations allowed)
__device__ float g_B1[VNUM*NVAR*CCAT*H1N];
__device__ float g_C1[VNUM*H1N];
__device__ float g_D1[VNUM*NVAR*H1N];   // delta per bit position b (0..13)
__device__ float g_E1[VNUM*H1N];        // base = C1 + sum_j B1[j,0]

// ---------------------------------------------------------------------------
// Precompute B1[v,j,c,:] = (latent[j,c] @ lin_w[v, j*ED:(j+1)*ED, :]) @ W1[v]
// ---------------------------------------------------------------------------
__global__ void precompute_B1_kernel(const float* __restrict__ lat,
                                     const float* __restrict__ lin_w,
                                     const float* __restrict__ w1) {
    int b = blockIdx.x;            // v*NVAR*CCAT + j*CCAT + c
    int v = b / (NVAR*CCAT);
    int jc = b % (NVAR*CCAT);
    int j = jc / CCAT, c = jc % CCAT;
    __shared__ float A[4*DDIM];    // 64
    int t = threadIdx.x;
    if (t < 4*DDIM) {
        float a = 0.f;
        const float* L = lat + (j*CCAT + c)*EDIM;
        const float* W = lin_w + (size_t)v*(NVAR*EDIM*4*DDIM) + (size_t)(j*EDIM)*(4*DDIM) + t;
        #pragma unroll
        for (int e = 0; e < EDIM; e++) a += L[e] * W[e*(4*DDIM)];
        A[t] = a;
    }
    __syncthreads();
    if (t < H1N) {
        float s = 0.f;
        const float* W1 = w1 + (size_t)v*(4*DDIM*H1N) + t;
        #pragma unroll 8
        for (int i = 0; i < 4*DDIM; i++) s += A[i] * W1[i*H1N];
        g_B1[(size_t)b*H1N + t] = s;
    }
}

__global__ void precompute_C1_kernel(const float* __restrict__ lin_b,
                                     const float* __restrict__ w1,
                                     const float* __restrict__ b1) {
    int v = blockIdx.x;
    int t = threadIdx.x;           // 0..287
    float s = b1[v*H1CH + t/H1SP];
    const float* W1 = w1 + (size_t)v*(4*DDIM*H1N) + t;
    const float* lb = lin_b + v*(4*DDIM);
    #pragma unroll 8
    for (int i = 0; i < 4*DDIM; i++) s += lb[i] * W1[i*H1N];
    g_C1[v*H1N + t] = s;
}

// D1[v, b, :] = B1[v, j=13-b, 1, :] - B1[v, j=13-b, 0, :]
// E1[v, :]    = C1[v, :] + sum_j B1[v, j, 0, :]
__global__ void precompute_D1E1_kernel() {
    int v = blockIdx.x;
    int t = threadIdx.x;  // 0..287
    float e = g_C1[v*H1N + t];
    #pragma unroll
    for (int j = 0; j < NVAR; j++) {
        float b0 = g_B1[(size_t)((v*NVAR + j)*CCAT + 0)*H1N + t];
        float b1v = g_B1[(size_t)((v*NVAR + j)*CCAT + 1)*H1N + t];
        e += b0;
        int b = NVAR - 1 - j;    // bit position for variable j
        g_D1[(size_t)(v*NVAR + b)*H1N + t] = b1v - b0;
    }
    g_E1[v*H1N + t] = e;
}

// ---------------------------------------------------------------------------
// Main kernel: one warp per contiguous state range; per-v constants in shared.
// ---------------------------------------------------------------------------

// shared layout in floats (all vector-accessed region starts are 16B aligned)
#define S_D1  0
#define S_E1  (S_D1 + NVAR*H1N)           // +4032  -> 4032
#define S_W2  (S_E1 + H1N)                // +288   -> 4320
#define S_W3  (S_W2 + H1CH*W2N)           // +4608  -> 8928
#define S_B2  (S_W3 + H2CH*12)            // +192   -> 9120
#define S_X   (S_B2 + 16)                 // +16    -> 9136
#define S_H1S (S_X + BBATCH*MN)           // +1568  -> 10704 (16-float aligned)
#define S_H2  (S_H1S + WARPS*H1CH*12)     // +3072  -> 13776
#define S_M   (S_H2 + WARPS*H2N)          // +3200  -> 16976
#define SMEM_FLOATS (S_M + WARPS*GRP*MROW) // +1664 -> 18640 floats = 74560 B

__device__ __forceinline__ float elu_f(float x) {
    return x > 0.f ? x : (__expf(x) - 1.f);
}

__global__ void __launch_bounds__(WARPS*32, 3)
emission_main_kernel(const float* __restrict__ x,
                     const float* __restrict__ w2,
                     const float* __restrict__ b2,
                     const float* __restrict__ w3,
                     const float* __restrict__ b3,
                     float* __restrict__ out) {
    extern __shared__ float smem[];
    const int tid  = threadIdx.x;
    const int lane = tid & 31;
    const int warp = tid >> 5;
    const int v    = blockIdx.x / BLOCKS_PER_V;
    const int blk  = blockIdx.x % BLOCKS_PER_V;

    // ---- stage in per-v constants ----
    for (int i = tid; i < NVAR*H1N; i += blockDim.x)
        smem[S_D1 + i] = g_D1[(size_t)v*(NVAR*H1N) + i];
    for (int i = tid; i < H1N; i += blockDim.x)
        smem[S_E1 + i] = g_E1[v*H1N + i];
    for (int i = tid; i < H1CH*W2N; i += blockDim.x)
        smem[S_W2 + i] = w2[(size_t)v*(H1CH*W2N) + i];
    // w3 padded: 9 taps per channel stored in 12-float rows (rows 16B aligned)
    if (tid < H2CH*KSZ*KSZ) {
        int i = tid / 9, t = tid % 9;
        smem[S_W3 + i*12 + t] = w3[(size_t)v*(H2CH*KSZ*KSZ) + tid];
    }
    if (tid < H2CH) smem[S_B2 + tid] = b2[v*H2CH + tid];
    for (int i = tid; i < BBATCH*MN; i += blockDim.x) {
        int bb = i / MN, p = i % MN;
        smem[S_X + i] = x[(size_t)bb*(VNUM*MN) + v*MN + p];
    }
    __syncthreads();

    float* __restrict__ sD1 = smem + S_D1;
    float* __restrict__ sE1 = smem + S_E1;
    float* __restrict__ sW2 = smem + S_W2;
    float* __restrict__ sW3 = smem + S_W3;
    float* __restrict__ sB2 = smem + S_B2;
    float* __restrict__ sX  = smem + S_X;
    float* __restrict__ h1w = smem + S_H1S + warp*(H1CH*12);
    float* __restrict__ h2w = smem + S_H2 + warp*H2N;
    float* __restrict__ mg  = smem + S_M  + warp*(GRP*MROW);
    const float bias3 = b3[v];

    // contiguous state range for this warp
    const int wid    = blk*WARPS + warp;
    const int nst    = QSTATES + (wid < RSTATES ? 1 : 0);
    const int start  = wid*QSTATES + (wid < RSTATES ? wid : RSTATES);

    // ---- build initial pre-ELU h1 in registers ----
    float h1pre[9];
    {
        const float* ep = sE1 + lane*H1SP;
        #pragma unroll
        for (int q = 0; q < 9; q++) h1pre[q] = ep[q];
        #pragma unroll
        for (int b = 0; b < NVAR; b++) {
            if ((start >> b) & 1) {
                const float* dp = sD1 + b*H1N + lane*H1SP;
                #pragma unroll
                for (int q = 0; q < 9; q++) h1pre[q] += dp[q];
            }
        }
    }

    for (int g0 = 0; g0 < nst; g0 += GRP) {
        const int gs = (nst - g0 < GRP) ? (nst - g0) : GRP;
        const int s0 = start + g0;

        for (int si = 0; si < gs; si++) {
            const int s = s0 + si;
            float* __restrict__ mw = mg + si*MROW;

            // ---- incremental update: flip the bits that changed (avg ~2) ----
            if (g0 + si) {
                unsigned diff = (unsigned)(s ^ (s - 1));
                do {
                    int b = __ffs(diff) - 1;
                    diff &= diff - 1;
                    float sg = ((s >> b) & 1) ? 1.f : -1.f;
                    const float* dp = sD1 + b*H1N + lane*H1SP;
                    #pragma unroll
                    for (int q = 0; q < 9; q++) h1pre[q] = fmaf(sg, dp[q], h1pre[q]);
                } while (diff);
            }

            // ---- ELU + publish h1 (lane = channel) to padded smem row ----
            {
                float4 p0, p1;
                p0.x = elu_f(h1pre[0]); p0.y = elu_f(h1pre[1]);
                p0.z = elu_f(h1pre[2]); p0.w = elu_f(h1pre[3]);
                p1.x = elu_f(h1pre[4]); p1.y = elu_f(h1pre[5]);
                p1.z = elu_f(h1pre[6]); p1.w = elu_f(h1pre[7]);
                float p8 = elu_f(h1pre[8]);
                float* row = h1w + lane*12;
                *(float4*)(row)     = p0;
                *(float4*)(row + 4) = p1;
                row[8] = p8;
            }

            // ---- zero h2 accumulator (bias folded into conv3's ELU load) ----
            for (int idx = lane; idx < H2N; idx += 32)
                h2w[idx] = 0.f;
            __syncwarp();

            // ---- conv2 as 9 K=32 -> N=144 products; packed f32x2 math.
            //      aP[j][k] holds the (q=2j, q=2j+1) pair for weight slot k. ----
            unsigned long long aP[4][5];
            float a8[5];
            #pragma unroll
            for (int j = 0; j < 4; j++)
                #pragma unroll
                for (int k = 0; k < 5; k++) aP[j][k] = 0ull;
            #pragma unroll
            for (int k = 0; k < 5; k++) a8[k] = 0.f;

            #pragma unroll 4
            for (int i = 0; i < H1CH; i++) {
                const ulonglong2* hv = (const ulonglong2*)(h1w + i*12);
                ulonglong2 hAB = hv[0];     // (h0,h1) (h2,h3)
                ulonglong2 hCD = hv[1];     // (h4,h5) (h6,h7)
                float hc = h1w[i*12 + 8];
                const float* wrow = sW2 + i*W2N;
                float wr0 = wrow[lane];
                float wr1 = wrow[lane + 32];
                float wr2 = wrow[lane + 64];
                float wr3 = wrow[lane + 96];
                float wr4 = (lane < 16) ? wrow[lane + 128] : 0.f;
                #pragma unroll
                for (int k = 0; k < 5; k++) {
                    float wk = (k==0)?wr0:(k==1)?wr1:(k==2)?wr2:(k==3)?wr3:wr4;
                    unsigned long long wp;
                    PACK2(wp, wk);
                    FMA2(aP[0][k], wp, hAB.x, aP[0][k]);
                    FMA2(aP[1][k], wp, hAB.y, aP[1][k]);
                    FMA2(aP[2][k], wp, hCD.x, aP[2][k]);
                    FMA2(aP[3][k], wp, hCD.y, aP[3][k]);
                    a8[k] = fmaf(wk, hc, a8[k]);
                }
            }

            // ---- scatter into h2: unpack pairs lazily, one sync per q ----
            #pragma unroll
            for (int j = 0; j < 4; j++) {
                float lo[5], hi[5];
                #pragma unroll
                for (int k = 0; k < 5; k++) UNPK2(lo[k], hi[k], aP[j][k]);
                {
                    const int q = 2*j;
                    const int u = q / 3, vx = q % 3;
                    #pragma unroll
                    for (int k = 0; k < 5; k++) {
                        const int e = lane + 32*k;
                        if (e < W2N) {
                            const int o = e / 9, t = e % 9;
                            const int ky = t / 3, kx = t % 3;
                            h2w[o*H2SP + (u+ky)*5 + (vx+kx)] += lo[k];
                        }
                    }
                    __syncwarp();
                }
                {
                    const int q = 2*j + 1;
                    const int u = q / 3, vx = q % 3;
                    #pragma unroll
                    for (int k = 0; k < 5; k++) {
                        const int e = lane + 32*k;
                        if (e < W2N) {
                            const int o = e / 9, t = e % 9;
                            const int ky = t / 3, kx = t % 3;
                            h2w[o*H2SP + (u+ky)*5 + (vx+kx)] += hi[k];
                        }
                    }
                    __syncwarp();
                }
            }
            {   // q = 8
                const int u = 2, vx = 2;
                #pragma unroll
                for (int k = 0; k < 5; k++) {
                    const int e = lane + 32*k;
                    if (e < W2N) {
                        const int o = e / 9, t = e % 9;
                        const int ky = t / 3, kx = t % 3;
                        h2w[o*H2SP + (u+ky)*5 + (vx+kx)] += a8[k];
                    }
                }
                __syncwarp();
            }

            // ---- init m with bias3 ----
            for (int idx = lane; idx < MN; idx += 32)
                mw[idx] = bias3;
            __syncwarp();

            // ---- conv3: lane = input position; bias+ELU fused; broadcast
            //      float4 weight loads; 9 conflict-free RMW scatter rounds ----
            if (lane < H2SP) {
                const int u  = lane / 5, vv = lane % 5;
                float4 b2a = *(const float4*)(sB2);
                float4 b2b = *(const float4*)(sB2 + 4);
                float4 b2c = *(const float4*)(sB2 + 8);
                float4 b2d = *(const float4*)(sB2 + 12);
                float b2r[16] = {b2a.x,b2a.y,b2a.z,b2a.w, b2b.x,b2b.y,b2b.z,b2b.w,
                                 b2c.x,b2c.y,b2c.z,b2c.w, b2d.x,b2d.y,b2d.z,b2d.w};
                float val[9];
                #pragma unroll
                for (int t = 0; t < 9; t++) val[t] = 0.f;
                #pragma unroll
                for (int i = 0; i < H2CH; i++) {
                    float h = elu_f(h2w[i*H2SP + lane] + b2r[i]);
                    const float* wrow = sW3 + i*12;
                    float4 wA = *(const float4*)(wrow);
                    float4 wB = *(const float4*)(wrow + 4);
                    float  w8 = wrow[8];
                    val[0] += h * wA.x;
                    val[1] += h * wA.y;
                    val[2] += h * wA.z;
                    val[3] += h * wA.w;
                    val[4] += h * wB.x;
                    val[5] += h * wB.y;
                    val[6] += h * wB.z;
                    val[7] += h * wB.w;
                    val[8] += h * w8;
                }
                #pragma unroll
                for (int t = 0; t < 9; t++) {
                    const int ky = t / 3, kx = t % 3;
                    mw[(u+ky)*7 + (vv+kx)] += val[t];   // distinct addrs per round
                    __syncwarp(0x01ffffffu);
                }
            }
            __syncwarp();
        }

        // ---- group loss vs all 32 images: lane = batch; x read ONCE per
        //      group, m rows via broadcast float4 loads ----
        {
            float accb[GRP];
            #pragma unroll
            for (int si = 0; si < GRP; si++) accb[si] = 0.f;
            const float* xp = sX + lane*MN;

            if (gs == GRP) {
                #pragma unroll
                for (int j = 0; j < 12; j++) {
                    float x0 = xp[4*j + 0];
                    float x1 = xp[4*j + 1];
                    float x2 = xp[4*j + 2];
                    float x3 = xp[4*j + 3];
                    #pragma unroll
                    for (int si = 0; si < GRP; si++) {
                        float4 mv = *(const float4*)(mg + si*MROW + 4*j);
                        float d0 = mv.x - x0;
                        float d1 = mv.y - x1;
                        float d2 = mv.z - x2;
                        float d3 = mv.w - x3;
                        accb[si] += d0*d0 + d1*d1 + d2*d2 + d3*d3;
                    }
                }
                float x48 = xp[48];
                #pragma unroll
                for (int si = 0; si < GRP; si++) {
                    float d = mg[si*MROW + 48] - x48;
                    accb[si] += d*d;
                    out[(size_t)lane*(KSTATES*VNUM) + (size_t)(s0+si)*VNUM + v] =
                        -0.5f * (accb[si]);
                }
            } else {
                for (int si = 0; si < gs; si++) {
                    float a = 0.f;
                    const float* mp = mg + si*MROW;
                    #pragma unroll 7
                    for (int p = 0; p < MN; p++) {
                        float d = mp[p] - xp[p];
                        a += d*d;
                    }
                    out[(size_t)lane*(KSTATES*VNUM) + (size_t)(s0+si)*VNUM + v] =
                        -0.5f * a;
                }
            }
        }
        __syncwarp();
    }
}

// ---------------------------------------------------------------------------
extern "C" void kernel_launch(void* const* d_in, const int* in_sizes, int n_in,
                              void* d_out, int out_size) {
    const float* x     = (const float*)d_in[0];
    const float* lat   = (const float*)d_in[1];
    const float* lin_w = (const float*)d_in[2];
    const float* lin_b = (const float*)d_in[3];
    const float* w1    = (const float*)d_in[4];
    const float* b1    = (const float*)d_in[5];
    const float* w2    = (const float*)d_in[6];
    const float* b2    = (const float*)d_in[7];
    const float* w3    = (const float*)d_in[8];
    const float* b3    = (const float*)d_in[9];
    float* out = (float*)d_out;

    (void)in_sizes; (void)n_in; (void)out_size;

    precompute_B1_kernel<<<VNUM*NVAR*CCAT, H1N>>>(lat, lin_w, w1);
    precompute_C1_kernel<<<VNUM, H1N>>>(lin_b, w1, b1);
    precompute_D1E1_kernel<<<VNUM, H1N>>>();

    cudaFuncSetAttribute(emission_main_kernel,
                         cudaFuncAttributeMaxDynamicSharedMemorySize,
                         SMEM_FLOATS * (int)sizeof(float));

    emission_main_kernel<<<VNUM*BLOCKS_PER_V, WARPS*32, SMEM_FLOATS*sizeof(float)>>>(
        x, w2, b2, w3, b3, out);
}

// round 16
// speedup vs baseline: 1.0806x; 1.0012x over previous
#include <cuda_runtime.h>

// Problem constants
#define NVAR 14
#define CCAT 2
#define EDIM 32
#define VNUM 3
#define DDIM 16
#define KSZ  3
#define KSTATES 16384      // 2^14
#define BBATCH 32

#define H1CH 32            // conv1 out channels (2*D)
#define H1SP 9             // 3x3
#define H1N  (H1CH*H1SP)   // 288
#define H2CH 16            // conv2 out channels (D)
#define H2SP 25            // 5x5
#define H2N  (H2CH*H2SP)   // 400
#define W2N  (H2CH*KSZ*KSZ) // 144 entries per input channel
#define MN   49            // 7x7
#define MROW 52            // padded m row (16B-aligned float4 rows)
#define GRP  4             // states per loss group

#define WARPS 8
#define BLOCKS_PER_V 148
#define TOTAL_WARPS_PER_V (BLOCKS_PER_V*WARPS)        // 1184
#define QSTATES (KSTATES / TOTAL_WARPS_PER_V)         // 13
#define RSTATES (KSTATES - QSTATES*TOTAL_WARPS_PER_V) // 992

// Packed f32x2 helpers (Blackwell): 2 fp32 MACs per fma-pipe issue slot.
#define FMA2(d, a, b, c) \
    asm("fma.rn.f32x2 %0, %1, %2, %3;" : "=l"(d) : "l"(a), "l"(b), "l"(c))
#define PACK2(out, f) \
    asm("mov.b64 %0, {%1, %1};" : "=l"(out) : "f"(f))
#define UNPK2(lo, hi, in) \
    asm("mov.b64 {%0, %1}, %2;" : "=f"(lo), "=f"(hi) : "l"(in))

// Precomputed scratch (no allocations allowed)
__device__ float g_B1[VNUM*NVAR*CCAT*H1N];
__device__ float g_C1[VNUM*H1N];
__device__ float g_D1[VNUM*NVAR*H1N];   // delta per bit position b (0..13)
__device__ float g_E1[VNUM*H1N];        // base = C1 + sum_j B1[j,0]

// ---------------------------------------------------------------------------
// Precompute B1[v,j,c,:] = (latent[j,c] @ lin_w[v, j*ED:(j+1)*ED, :]) @ W1[v]
// ---------------------------------------------------------------------------
__global__ void precompute_B1_kernel(const float* __restrict__ lat,
                                     const float* __restrict__ lin_w,
                                     const float* __restrict__ w1) {
    int b = blockIdx.x;            // v*NVAR*CCAT + j*CCAT + c
    int v = b / (NVAR*CCAT);
    int jc = b % (NVAR*CCAT);
    int j = jc / CCAT, c = jc % CCAT;
    __shared__ float A[4*DDIM];    // 64
    int t = threadIdx.x;
    if (t < 4*DDIM) {
        float a = 0.f;
        const float* L = lat + (j*CCAT + c)*EDIM;
        const float* W = lin_w + (size_t)v*(NVAR*EDIM*4*DDIM) + (size_t)(j*EDIM)*(4*DDIM) + t;
        #pragma unroll
        for (int e = 0; e < EDIM; e++) a += L[e] * W[e*(4*DDIM)];
        A[t] = a;
    }
    __syncthreads();
    if (t < H1N) {
        float s = 0.f;
        const float* W1 = w1 + (size_t)v*(4*DDIM*H1N) + t;
        #pragma unroll 8
        for (int i = 0; i < 4*DDIM; i++) s += A[i] * W1[i*H1N];
        g_B1[(size_t)b*H1N + t] = s;
    }
}

__global__ void precompute_C1_kernel(const float* __restrict__ lin_b,
                                     const float* __restrict__ w1,
                                     const float* __restrict__ b1) {
    int v = blockIdx.x;
    int t = threadIdx.x;           // 0..287
    float s = b1[v*H1CH + t/H1SP];
    const float* W1 = w1 + (size_t)v*(4*DDIM*H1N) + t;
    const float* lb = lin_b + v*(4*DDIM);
    #pragma unroll 8
    for (int i = 0; i < 4*DDIM; i++) s += lb[i] * W1[i*H1N];
    g_C1[v*H1N + t] = s;
}

// D1[v, b, :] = B1[v, j=13-b, 1, :] - B1[v, j=13-b, 0, :]
// E1[v, :]    = C1[v, :] + sum_j B1[v, j, 0, :]
__global__ void precompute_D1E1_kernel() {
    int v = blockIdx.x;
    int t = threadIdx.x;  // 0..287
    float e = g_C1[v*H1N + t];
    #pragma unroll
    for (int j = 0; j < NVAR; j++) {
        float b0 = g_B1[(size_t)((v*NVAR + j)*CCAT + 0)*H1N + t];
        float b1v = g_B1[(size_t)((v*NVAR + j)*CCAT + 1)*H1N + t];
        e += b0;
        int b = NVAR - 1 - j;    // bit position for variable j
        g_D1[(size_t)(v*NVAR + b)*H1N + t] = b1v - b0;
    }
    g_E1[v*H1N + t] = e;
}

// ---------------------------------------------------------------------------
// Main kernel: one warp per contiguous state range; per-v constants in shared.
// ---------------------------------------------------------------------------

// shared layout in floats (all vector-accessed region starts are 16B aligned)
#define S_D1  0
#define S_E1  (S_D1 + NVAR*H1N)           // +4032  -> 4032
#define S_W2  (S_E1 + H1N)                // +288   -> 4320
#define S_W3  (S_W2 + H1CH*W2N)           // +4608  -> 8928
#define S_B2  (S_W3 + H2CH*12)            // +192   -> 9120
#define S_X   (S_B2 + 16)                 // +16    -> 9136
#define S_H1S (S_X + BBATCH*MN)           // +1568  -> 10704 (16-float aligned)
#define S_H2  (S_H1S + WARPS*H1CH*12)     // +3072  -> 13776
#define S_M   (S_H2 + WARPS*H2N)          // +3200  -> 16976
#define SMEM_FLOATS (S_M + WARPS*GRP*MROW) // +1664 -> 18640 floats = 74560 B

__device__ __forceinline__ float elu_f(float x) {
    return x > 0.f ? x : (__expf(x) - 1.f);
}

__global__ void __launch_bounds__(WARPS*32, 3)
emission_main_kernel(const float* __restrict__ x,
                     const float* __restrict__ w2,
                     const float* __restrict__ b2,
                     const float* __restrict__ w3,
                     const float* __restrict__ b3,
                     float* __restrict__ out) {
    extern __shared__ float smem[];
    const int tid  = threadIdx.x;
    const int lane = tid & 31;
    const int warp = tid >> 5;
    const int v    = blockIdx.x / BLOCKS_PER_V;
    const int blk  = blockIdx.x % BLOCKS_PER_V;

    // ---- stage in per-v constants ----
    for (int i = tid; i < NVAR*H1N; i += blockDim.x)
        smem[S_D1 + i] = g_D1[(size_t)v*(NVAR*H1N) + i];
    for (int i = tid; i < H1N; i += blockDim.x)
        smem[S_E1 + i] = g_E1[v*H1N + i];
    for (int i = tid; i < H1CH*W2N; i += blockDim.x)
        smem[S_W2 + i] = w2[(size_t)v*(H1CH*W2N) + i];
    // w3 padded: 9 taps per channel stored in 12-float rows (rows 16B aligned)
    if (tid < H2CH*KSZ*KSZ) {
        int i = tid / 9, t = tid % 9;
        smem[S_W3 + i*12 + t] = w3[(size_t)v*(H2CH*KSZ*KSZ) + tid];
    }
    if (tid < H2CH) smem[S_B2 + tid] = b2[v*H2CH + tid];
    for (int i = tid; i < BBATCH*MN; i += blockDim.x) {
        int bb = i / MN, p = i % MN;
        smem[S_X + i] = x[(size_t)bb*(VNUM*MN) + v*MN + p];
    }
    __syncthreads();

    float* __restrict__ sD1 = smem + S_D1;
    float* __restrict__ sE1 = smem + S_E1;
    float* __restrict__ sW2 = smem + S_W2;
    float* __restrict__ sW3 = smem + S_W3;
    float* __restrict__ sB2 = smem + S_B2;
    float* __restrict__ sX  = smem + S_X;
    float* __restrict__ h1w = smem + S_H1S + warp*(H1CH*12);
    float* __restrict__ h2w = smem + S_H2 + warp*H2N;
    float* __restrict__ mg  = smem + S_M  + warp*(GRP*MROW);
    const float bias3 = b3[v];

    // contiguous state range for this warp
    const int wid    = blk*WARPS + warp;
    const int nst    = QSTATES + (wid < RSTATES ? 1 : 0);
    const int start  = wid*QSTATES + (wid < RSTATES ? wid : RSTATES);

    // ---- build initial pre-ELU h1 in registers ----
    float h1pre[9];
    {
        const float* ep = sE1 + lane*H1SP;
        #pragma unroll
        for (int q = 0; q < 9; q++) h1pre[q] = ep[q];
        #pragma unroll
        for (int b = 0; b < NVAR; b++) {
            if ((start >> b) & 1) {
                const float* dp = sD1 + b*H1N + lane*H1SP;
                #pragma unroll
                for (int q = 0; q < 9; q++) h1pre[q] += dp[q];
            }
        }
    }

    for (int g0 = 0; g0 < nst; g0 += GRP) {
        const int gs = (nst - g0 < GRP) ? (nst - g0) : GRP;
        const int s0 = start + g0;

        for (int si = 0; si < gs; si++) {
            const int s = s0 + si;
            float* __restrict__ mw = mg + si*MROW;

            // ---- incremental update: flip the bits that changed (avg ~2) ----
            if (g0 + si) {
                unsigned diff = (unsigned)(s ^ (s - 1));
                do {
                    int b = __ffs(diff) - 1;
                    diff &= diff - 1;
                    float sg = ((s >> b) & 1) ? 1.f : -1.f;
                    const float* dp = sD1 + b*H1N + lane*H1SP;
                    #pragma unroll
                    for (int q = 0; q < 9; q++) h1pre[q] = fmaf(sg, dp[q], h1pre[q]);
                } while (diff);
            }

            // ---- ELU + publish h1 (lane = channel) to padded smem row ----
            {
                float4 p0, p1;
                p0.x = elu_f(h1pre[0]); p0.y = elu_f(h1pre[1]);
                p0.z = elu_f(h1pre[2]); p0.w = elu_f(h1pre[3]);
                p1.x = elu_f(h1pre[4]); p1.y = elu_f(h1pre[5]);
                p1.z = elu_f(h1pre[6]); p1.w = elu_f(h1pre[7]);
                float p8 = elu_f(h1pre[8]);
                float* row = h1w + lane*12;
                *(float4*)(row)     = p0;
                *(float4*)(row + 4) = p1;
                row[8] = p8;
            }

            // ---- zero h2 accumulator (bias folded into conv3's ELU load) ----
            for (int idx = lane; idx < H2N; idx += 32)
                h2w[idx] = 0.f;
            __syncwarp();

            // ---- conv2 as 9 K=32 -> N=144 products; packed f32x2 math.
            //      aP[j][k] holds the (q=2j, q=2j+1) pair for weight slot k. ----
            unsigned long long aP[4][5];
            float a8[5];
            #pragma unroll
            for (int j = 0; j < 4; j++)
                #pragma unroll
                for (int k = 0; k < 5; k++) aP[j][k] = 0ull;
            #pragma unroll
            for (int k = 0; k < 5; k++) a8[k] = 0.f;

            #pragma unroll 4
            for (int i = 0; i < H1CH; i++) {
                const ulonglong2* hv = (const ulonglong2*)(h1w + i*12);
                ulonglong2 hAB = hv[0];     // (h0,h1) (h2,h3)
                ulonglong2 hCD = hv[1];     // (h4,h5) (h6,h7)
                float hc = h1w[i*12 + 8];
                const float* wrow = sW2 + i*W2N;
                float wr0 = wrow[lane];
                float wr1 = wrow[lane + 32];
                float wr2 = wrow[lane + 64];
                float wr3 = wrow[lane + 96];
                float wr4 = (lane < 16) ? wrow[lane + 128] : 0.f;
                #pragma unroll
                for (int k = 0; k < 5; k++) {
                    float wk = (k==0)?wr0:(k==1)?wr1:(k==2)?wr2:(k==3)?wr3:wr4;
                    unsigned long long wp;
                    PACK2(wp, wk);
                    FMA2(aP[0][k], wp, hAB.x, aP[0][k]);
                    FMA2(aP[1][k], wp, hAB.y, aP[1][k]);
                    FMA2(aP[2][k], wp, hCD.x, aP[2][k]);
                    FMA2(aP[3][k], wp, hCD.y, aP[3][k]);
                    a8[k] = fmaf(wk, hc, a8[k]);
                }
            }

            // ---- scatter into h2: unpack pairs lazily, one sync per q ----
            #pragma unroll
            for (int j = 0; j < 4; j++) {
                float lo[5], hi[5];
                #pragma unroll
                for (int k = 0; k < 5; k++) UNPK2(lo[k], hi[k], aP[j][k]);
                {
                    const int q = 2*j;
                    const int u = q / 3, vx = q % 3;
                    #pragma unroll
                    for (int k = 0; k < 5; k++) {
                        const int e = lane + 32*k;
                        if (e < W2N) {
                            const int o = e / 9, t = e % 9;
                            const int ky = t / 3, kx = t % 3;
                            h2w[o*H2SP + (u+ky)*5 + (vx+kx)] += lo[k];
                        }
                    }
                    __syncwarp();
                }
                {
                    const int q = 2*j + 1;
                    const int u = q / 3, vx = q % 3;
                    #pragma unroll
                    for (int k = 0; k < 5; k++) {
                        const int e = lane + 32*k;
                        if (e < W2N) {
                            const int o = e / 9, t = e % 9;
                            const int ky = t / 3, kx = t % 3;
                            h2w[o*H2SP + (u+ky)*5 + (vx+kx)] += hi[k];
                        }
                    }
                    __syncwarp();
                }
            }
            {   // q = 8
                const int u = 2, vx = 2;
                #pragma unroll
                for (int k = 0; k < 5; k++) {
                    const int e = lane + 32*k;
                    if (e < W2N) {
                        const int o = e / 9, t = e % 9;
                        const int ky = t / 3, kx = t % 3;
                        h2w[o*H2SP + (u+ky)*5 + (vx+kx)] += a8[k];
                    }
                }
                __syncwarp();
            }

            // ---- init m with bias3 ----
            for (int idx = lane; idx < MN; idx += 32)
                mw[idx] = bias3;
            __syncwarp();

            // ---- conv3: lane = input position; bias+ELU fused; broadcast
            //      float4 weight loads; 9 conflict-free RMW scatter rounds ----
            if (lane < H2SP) {
                const int u  = lane / 5, vv = lane % 5;
                float4 b2a = *(const float4*)(sB2);
                float4 b2b = *(const float4*)(sB2 + 4);
                float4 b2c = *(const float4*)(sB2 + 8);
                float4 b2d = *(const float4*)(sB2 + 12);
                float b2r[16] = {b2a.x,b2a.y,b2a.z,b2a.w, b2b.x,b2b.y,b2b.z,b2b.w,
                                 b2c.x,b2c.y,b2c.z,b2c.w, b2d.x,b2d.y,b2d.z,b2d.w};
                float val[9];
                #pragma unroll
                for (int t = 0; t < 9; t++) val[t] = 0.f;
                #pragma unroll
                for (int i = 0; i < H2CH; i++) {
                    float h = elu_f(h2w[i*H2SP + lane] + b2r[i]);
                    const float* wrow = sW3 + i*12;
                    float4 wA = *(const float4*)(wrow);
                    float4 wB = *(const float4*)(wrow + 4);
                    float  w8 = wrow[8];
                    val[0] += h * wA.x;
                    val[1] += h * wA.y;
                    val[2] += h * wA.z;
                    val[3] += h * wA.w;
                    val[4] += h * wB.x;
                    val[5] += h * wB.y;
                    val[6] += h * wB.z;
                    val[7] += h * wB.w;
                    val[8] += h * w8;
                }
                #pragma unroll
                for (int t = 0; t < 9; t++) {
                    const int ky = t / 3, kx = t % 3;
                    mw[(u+ky)*7 + (vv+kx)] += val[t];   // distinct addrs per round
                    __syncwarp(0x01ffffffu);
                }
            }
            __syncwarp();
        }

        // ---- group loss vs all 32 images: lane = batch; x read ONCE per
        //      group, m rows via broadcast float4 loads ----
        {
            float accb[GRP];
            #pragma unroll
            for (int si = 0; si < GRP; si++) accb[si] = 0.f;
            const float* xp = sX + lane*MN;

            if (gs == GRP) {
                #pragma unroll
                for (int j = 0; j < 12; j++) {
                    float x0 = xp[4*j + 0];
                    float x1 = xp[4*j + 1];
                    float x2 = xp[4*j + 2];
                    float x3 = xp[4*j + 3];
                    #pragma unroll
                    for (int si = 0; si < GRP; si++) {
                        float4 mv = *(const float4*)(mg + si*MROW + 4*j);
                        float d0 = mv.x - x0;
                        float d1 = mv.y - x1;
                        float d2 = mv.z - x2;
                        float d3 = mv.w - x3;
                        accb[si] += d0*d0 + d1*d1 + d2*d2 + d3*d3;
                    }
                }
                float x48 = xp[48];
                #pragma unroll
                for (int si = 0; si < GRP; si++) {
                    float d = mg[si*MROW + 48] - x48;
                    accb[si] += d*d;
                    out[(size_t)lane*(KSTATES*VNUM) + (size_t)(s0+si)*VNUM + v] =
                        -0.5f * (accb[si]);
                }
            } else {
                for (int si = 0; si < gs; si++) {
                    float a = 0.f;
                    const float* mp = mg + si*MROW;
                    #pragma unroll 7
                    for (int p = 0; p < MN; p++) {
                        float d = mp[p] - xp[p];
                        a += d*d;
                    }
                    out[(size_t)lane*(KSTATES*VNUM) + (size_t)(s0+si)*VNUM + v] =
                        -0.5f * a;
                }
            }
        }
        __syncwarp();
    }
}

// ---------------------------------------------------------------------------
extern "C" void kernel_launch(void* const* d_in, const int* in_sizes, int n_in,
                              void* d_out, int out_size) {
    const float* x     = (const float*)d_in[0];
    const float* lat   = (const float*)d_in[1];
    const float* lin_w = (const float*)d_in[2];
    const float* lin_b = (const float*)d_in[3];
    const float* w1    = (const float*)d_in[4];
    const float* b1    = (const float*)d_in[5];
    const float* w2    = (const float*)d_in[6];
    const float* b2    = (const float*)d_in[7];
    const float* w3    = (const float*)d_in[8];
    const float* b3    = (const float*)d_in[9];
    float* out = (float*)d_out;

    (void)in_sizes; (void)n_in; (void)out_size;

    precompute_B1_kernel<<<VNUM*NVAR*CCAT, H1N>>>(lat, lin_w, w1);
    precompute_C1_kernel<<<VNUM, H1N>>>(lin_b, w1, b1);
    precompute_D1E1_kernel<<<VNUM, H1N>>>();

    cudaFuncSetAttribute(emission_main_kernel,
                         cudaFuncAttributeMaxDynamicSharedMemorySize,
                         SMEM_FLOATS * (int)sizeof(float));

    emission_main_kernel<<<VNUM*BLOCKS_PER_V, WARPS*32, SMEM_FLOATS*sizeof(float)>>>(
        x, w2, b2, w3, b3, out);
}